// round 6
// baseline (speedup 1.0000x reference)
#include <cuda_runtime.h>
#include <cuda_bf16.h>
#include <cstdint>

#define SP 7
#define MM 8
#define DD 1008
#define H0 256
#define H1 192
#define H2 160
#define NMAX 50400
#define GMAX (NMAX / SP)
#define BATCH (SP * MM)
#define HB 112
#define EB 1024

// ---------------- scratch (device globals; no allocation allowed) ------------
__device__ int d_idx[NMAX];
__device__ int d_hist[HB * SP];
__device__ int d_off[HB * SP];

// [hi | lo] split buffers, K-contiguous rows of width 2*K
__device__ __align__(16) __nv_bfloat16 d_a0[(size_t)NMAX * 2 * DD];
__device__ __align__(16) __nv_bfloat16 d_w0[(size_t)BATCH * H0 * 2 * DD];
__device__ __align__(16) __nv_bfloat16 d_w1[(size_t)BATCH * H1 * 2 * H0];
__device__ __align__(16) __nv_bfloat16 d_w2[(size_t)BATCH * H2 * 2 * H1];
__device__ __align__(16) __nv_bfloat16 d_a1[(size_t)BATCH * GMAX * 2 * H0];
__device__ __align__(16) __nv_bfloat16 d_a2[(size_t)BATCH * GMAX * 2 * H1];
__device__ float d_h2[(size_t)BATCH * GMAX * H2];
__device__ float d_part[EB];

__device__ __forceinline__ float celu_f(float x) {
    return x > 0.f ? x : 0.1f * expm1f(x * 10.0f);
}

// ---------------- PTX helpers (all baseline sm_80+ features) ------------------
__device__ __forceinline__ uint32_t smem_u32(const void* p) {
    uint32_t a;
    asm("{ .reg .u64 t; cvta.to.shared.u64 t, %1; cvt.u32.u64 %0, t; }"
        : "=r"(a) : "l"(p));
    return a;
}
__device__ __forceinline__ void cp16(uint32_t s, const void* g) {
    asm volatile("cp.async.cg.shared.global [%0], [%1], 16;" :: "r"(s), "l"(g));
}
__device__ __forceinline__ void cp_commit() {
    asm volatile("cp.async.commit_group;" ::: "memory");
}
template <int N>
__device__ __forceinline__ void cp_wait() {
    asm volatile("cp.async.wait_group %0;" :: "n"(N) : "memory");
}
__device__ __forceinline__ void ldsm_x4(uint32_t& r0, uint32_t& r1,
                                        uint32_t& r2, uint32_t& r3, uint32_t a) {
    asm volatile("ldmatrix.sync.aligned.m8n8.x4.shared.b16 {%0,%1,%2,%3}, [%4];"
                 : "=r"(r0), "=r"(r1), "=r"(r2), "=r"(r3) : "r"(a));
}
__device__ __forceinline__ void ldsm_x2(uint32_t& r0, uint32_t& r1, uint32_t a) {
    asm volatile("ldmatrix.sync.aligned.m8n8.x2.shared.b16 {%0,%1}, [%2];"
                 : "=r"(r0), "=r"(r1) : "r"(a));
}
__device__ __forceinline__ void mma16816(float* c, const uint32_t* a, const uint32_t* b) {
    asm volatile(
        "mma.sync.aligned.m16n8k16.row.col.f32.bf16.bf16.f32 "
        "{%0,%1,%2,%3}, {%4,%5,%6,%7}, {%8,%9}, {%0,%1,%2,%3};"
        : "+f"(c[0]), "+f"(c[1]), "+f"(c[2]), "+f"(c[3])
        : "r"(a[0]), "r"(a[1]), "r"(a[2]), "r"(a[3]), "r"(b[0]), "r"(b[1]));
}

// ---------------- stable species bucketing (deterministic) -------------------
__global__ void k_hist(const int* __restrict__ sp, int n, int chunk) {
    __shared__ int h[SP];
    if (threadIdx.x < SP) h[threadIdx.x] = 0;
    __syncthreads();
    int b = blockIdx.x;
    int beg = b * chunk, end = min(n, beg + chunk);
    for (int i = beg + threadIdx.x; i < end; i += blockDim.x)
        atomicAdd(&h[sp[i]], 1);
    __syncthreads();
    if (threadIdx.x < SP) d_hist[b * SP + threadIdx.x] = h[threadIdx.x];
}
__global__ void k_scan(int G) {
    int s = threadIdx.x;
    if (s >= SP) return;
    int acc = s * G;
    for (int b = 0; b < HB; b++) { d_off[b * SP + s] = acc; acc += d_hist[b * SP + s]; }
}
__global__ void k_place(const int* __restrict__ sp, int n, int chunk) {
    if (threadIdx.x != 0) return;
    int b = blockIdx.x;
    int beg = b * chunk, end = min(n, beg + chunk);
    int loc[SP];
#pragma unroll
    for (int s = 0; s < SP; s++) loc[s] = d_off[b * SP + s];
    for (int i = beg; i < end; i++) d_idx[loc[sp[i]]++] = i;
}

// ---------------- prep: gather+split AEV, transpose+split weights ------------
__global__ void k_prep_aev(const float* __restrict__ aev) {
    int r = blockIdx.x;
    const float* src = aev + (size_t)d_idx[r] * DD;
    size_t dst = (size_t)r * (2 * DD);
    for (int k = threadIdx.x; k < DD; k += blockDim.x) {
        float v = src[k];
        __nv_bfloat16 h = __float2bfloat16(v);
        d_a0[dst + k] = h;
        d_a0[dst + DD + k] = __float2bfloat16(v - __bfloat162float(h));
    }
}

__global__ void k_wsplit(const float* __restrict__ W, int K, int N, int layer) {
    __shared__ float tile[32][33];
    int bm = blockIdx.z;
    int n0 = blockIdx.x * 32, k0 = blockIdx.y * 32;
    const float* Wp = W + (size_t)bm * K * N;
    for (int r = threadIdx.y; r < 32; r += 8) {
        int k = k0 + r, n = n0 + threadIdx.x;
        tile[r][threadIdx.x] = (k < K && n < N) ? Wp[(size_t)k * N + n] : 0.f;
    }
    __syncthreads();
    __nv_bfloat16* O;
    if (layer == 0)      O = d_w0;
    else if (layer == 1) O = d_w1;
    else                 O = d_w2;
    for (int r = threadIdx.y; r < 32; r += 8) {
        int n = n0 + r, k = k0 + threadIdx.x;
        if (n < N && k < K) {
            float v = tile[threadIdx.x][r];
            __nv_bfloat16 h = __float2bfloat16(v);
            size_t o = ((size_t)bm * N + n) * (size_t)(2 * K) + k;
            O[o] = h;
            O[o + K] = __float2bfloat16(v - __bfloat162float(h));
        }
    }
}

// ---------------- bf16 HMMA batched GEMM (3-term split via K sections) -------
// BM=256, BN=64, BK=16; 8 warps as 4(m) x 2(n): warp tile 64x32.
// D[256 x NOUT] = A[256 x K'] * W^T, K' = 3K as sections
//   s0: (Ah,Bh)  s1: (Al,Bh)  s2: (Ah,Bl)    [drops Al*Bl ~ 2^-18]
// Epilogue: +bias, CELU; LAYER<2 -> hi/lo split store, LAYER==2 -> fp32.
template <int K, int NOUT, int LAYER>
__global__ void __launch_bounds__(256, 1)
k_mma(const float* __restrict__ bias, int G) {
    constexpr int BM = 256, BN = 64;
    constexpr int KPS = K / 16;
    constexpr int TOTAL = 3 * KPS;
    constexpr int NS = 3;

    __shared__ __align__(16) __nv_bfloat16 As[NS][BM][24];  // 48B pitch
    __shared__ __align__(16) __nv_bfloat16 Bs[NS][BN][24];

    const int t = threadIdx.x;
    const int lane = t & 31;
    const int wid = t >> 5;
    const int wm = wid >> 1;   // 0..3 -> 64-row slab
    const int wn = wid & 1;    // 0..1 -> 32-col slab
    const int bm = blockIdx.z;
    const int gt = blockIdx.x * BM;
    const int ntb = blockIdx.y * BN;

    const __nv_bfloat16* Ag;
    const __nv_bfloat16* Wg;
    size_t aBase;
    if (LAYER == 0)      { Ag = d_a0; Wg = d_w0; aBase = (size_t)(bm / MM) * G; }
    else if (LAYER == 1) { Ag = d_a1; Wg = d_w1; aBase = (size_t)bm * G; }
    else                 { Ag = d_a2; Wg = d_w2; aBase = (size_t)bm * G; }

    // per-thread load sources (row clamped; garbage rows never stored)
    const int growc = min(gt + t, G - 1);
    const __nv_bfloat16* aSrc = Ag + ((size_t)(aBase + growc)) * (size_t)(2 * K);
    const int bn = min(ntb + (t >> 1), NOUT - 1);
    const __nv_bfloat16* bSrc =
        Wg + ((size_t)bm * NOUT + bn) * (size_t)(2 * K) + (t & 1) * 8;

    auto load_stage = [&](int st, int it) {
        int sec = it / KPS, w = it - sec * KPS;
        int ak = (sec == 1 ? K : 0) + w * 16;
        int bk = (sec == 2 ? K : 0) + w * 16;
        cp16(smem_u32(&As[st][t][0]), aSrc + ak);
        cp16(smem_u32(&As[st][t][8]), aSrc + ak + 8);
        if (t < 2 * BN) cp16(smem_u32(&Bs[st][t >> 1][(t & 1) * 8]), bSrc + bk);
        cp_commit();
    };

    float acc[4][4][4];
#pragma unroll
    for (int i = 0; i < 4; i++)
#pragma unroll
        for (int j = 0; j < 4; j++)
#pragma unroll
            for (int k = 0; k < 4; k++) acc[i][j][k] = 0.f;

    // ldmatrix lane address offsets (bytes), 48B row pitch
    const uint32_t aoff = (uint32_t)((wm * 64 + (lane & 15)) * 48 + (lane >> 4) * 16);
    const uint32_t boff = (uint32_t)((wn * 32 + (lane & 7)) * 48 + ((lane >> 3) & 1) * 16);

#pragma unroll 1
    for (int s = 0; s < NS - 1; s++) load_stage(s, s);

#pragma unroll 1
    for (int i = 0; i < TOTAL; i++) {
        cp_wait<NS - 2>();
        __syncthreads();
        if (i + NS - 1 < TOTAL) load_stage((i + NS - 1) % NS, i + NS - 1);
        else cp_commit();

        const int st = i % NS;
        const uint32_t ab = smem_u32(&As[st][0][0]);
        const uint32_t bb = smem_u32(&Bs[st][0][0]);
        uint32_t aF[4][4], bF[4][2];
#pragma unroll
        for (int mt = 0; mt < 4; mt++)
            ldsm_x4(aF[mt][0], aF[mt][1], aF[mt][2], aF[mt][3],
                    ab + aoff + mt * 16 * 48);
#pragma unroll
        for (int nt = 0; nt < 4; nt++)
            ldsm_x2(bF[nt][0], bF[nt][1], bb + boff + nt * 8 * 48);
#pragma unroll
        for (int mt = 0; mt < 4; mt++)
#pragma unroll
            for (int nt = 0; nt < 4; nt++)
                mma16816(acc[mt][nt], aF[mt], bF[nt]);
    }

    // -------- epilogue: bias + CELU (+ hi/lo resplit) --------
    const float* bp = bias + (size_t)bm * NOUT;
#pragma unroll
    for (int mt = 0; mt < 4; mt++) {
#pragma unroll
        for (int half = 0; half < 2; half++) {
            const int grow = gt + wm * 64 + mt * 16 + (lane >> 2) + half * 8;
            if (grow >= G) continue;
            size_t rb = ((size_t)bm * G + grow) *
                        (size_t)(LAYER < 2 ? 2 * NOUT : NOUT);
#pragma unroll
            for (int nt = 0; nt < 4; nt++) {
                const int col = ntb + wn * 32 + nt * 8 + (lane & 3) * 2;
                if (col >= NOUT) continue;
                float v0 = acc[mt][nt][half * 2 + 0] + __ldg(bp + col);
                float v1 = acc[mt][nt][half * 2 + 1] + __ldg(bp + col + 1);
                v0 = celu_f(v0);
                v1 = celu_f(v1);
                if (LAYER < 2) {
                    __nv_bfloat16 h0 = __float2bfloat16(v0);
                    __nv_bfloat16 h1 = __float2bfloat16(v1);
                    __nv_bfloat162 hh, ll;
                    hh.x = h0; hh.y = h1;
                    ll.x = __float2bfloat16(v0 - __bfloat162float(h0));
                    ll.y = __float2bfloat16(v1 - __bfloat162float(h1));
                    __nv_bfloat16* dst = (LAYER == 0) ? d_a1 : d_a2;
                    *(__nv_bfloat162*)(dst + rb + col) = hh;
                    *(__nv_bfloat162*)(dst + rb + NOUT + col) = ll;
                } else {
                    float2 vv; vv.x = v0; vv.y = v1;
                    *(float2*)(d_h2 + rb + col) = vv;
                }
            }
        }
    }
}

// ---------------- last layer (160 -> 1) + deterministic reduction ------------
__global__ void k_energy(const float* __restrict__ W3,
                         const float* __restrict__ b3, int G) {
    const int lane = threadIdx.x & 31;
    const int wid = threadIdx.x >> 5;
    const int nw = blockDim.x >> 5;
    const int gw = blockIdx.x * nw + wid;
    const int stride = gridDim.x * nw;
    const int R = BATCH * G;

    float sum = 0.f;
    for (int r = gw; r < R; r += stride) {
        const int bm = r / G;
        const int g = r - bm * G;
        const float* __restrict__ row = d_h2 + ((size_t)bm * G + g) * H2;
        const float* __restrict__ w = W3 + (size_t)bm * H2;
        float d = 0.f;
#pragma unroll
        for (int i = lane; i < H2; i += 32)
            d = fmaf(row[i], w[i], d);   // h2 already CELU'd in GEMM epilogue
#pragma unroll
        for (int off = 16; off > 0; off >>= 1)
            d += __shfl_xor_sync(0xFFFFFFFFu, d, off);
        if (lane == 0) sum += d + b3[bm];
    }
    __shared__ float ws[32];
    if (lane == 0) ws[wid] = sum;
    __syncthreads();
    if (threadIdx.x == 0) {
        float p = 0.f;
        for (int i = 0; i < nw; i++) p += ws[i];
        d_part[blockIdx.x] = p;
    }
}

__global__ void k_final(float* __restrict__ out) {
    __shared__ float sh[EB];
    const int tid = threadIdx.x;
    sh[tid] = d_part[tid];
    __syncthreads();
    for (int s = EB / 2; s > 0; s >>= 1) {
        if (tid < s) sh[tid] += sh[tid + s];
        __syncthreads();
    }
    if (tid == 0) out[0] = sh[0] * (1.0f / (float)MM);
}

// ---------------- harness entry ----------------------------------------------
extern "C" void kernel_launch(void* const* d_in, const int* in_sizes, int n_in,
                              void* d_out, int out_size) {
    const int* species = (const int*)d_in[0];
    const float* aev = (const float*)d_in[1];
    const float* W0 = (const float*)d_in[2];
    const float* b0 = (const float*)d_in[3];
    const float* W1 = (const float*)d_in[4];
    const float* b1 = (const float*)d_in[5];
    const float* W2 = (const float*)d_in[6];
    const float* b2 = (const float*)d_in[7];
    const float* W3 = (const float*)d_in[8];
    const float* b3 = (const float*)d_in[9];
    float* out = (float*)d_out;

    const int N = in_sizes[0];
    const int G = N / SP;
    const int chunk = (N + HB - 1) / HB;

    // bucketing
    k_hist<<<HB, 256>>>(species, N, chunk);
    k_scan<<<1, 32>>>(G);
    k_place<<<HB, 32>>>(species, N, chunk);

    // prep: gather+split AEV, transpose+split weights
    k_prep_aev<<<N, 256>>>(aev);
    {
        dim3 g0((H0 + 31) / 32, (DD + 31) / 32, BATCH);
        k_wsplit<<<g0, dim3(32, 8)>>>(W0, DD, H0, 0);
        dim3 g1((H1 + 31) / 32, (H0 + 31) / 32, BATCH);
        k_wsplit<<<g1, dim3(32, 8)>>>(W1, H0, H1, 1);
        dim3 g2((H2 + 31) / 32, (H1 + 31) / 32, BATCH);
        k_wsplit<<<g2, dim3(32, 8)>>>(W2, H1, H2, 2);
    }

    const int gtiles = (G + 255) / 256;
    k_mma<DD, H0, 0><<<dim3(gtiles, (H0 + 63) / 64, BATCH), 256>>>(b0, G);
    k_mma<H0, H1, 1><<<dim3(gtiles, (H1 + 63) / 64, BATCH), 256>>>(b1, G);
    k_mma<H1, H2, 2><<<dim3(gtiles, (H2 + 63) / 64, BATCH), 256>>>(b2, G);

    k_energy<<<EB, 256>>>(W3, b3, G);
    k_final<<<1, EB>>>(out);
}

// round 7
// speedup vs baseline: 1.3064x; 1.3064x over previous
#include <cuda_runtime.h>
#include <cuda_bf16.h>
#include <cstdint>

#define SP 7
#define MM 8
#define DD 1008
#define H0 256
#define H1 192
#define H2 160
#define NMAX 50400
#define GMAX (NMAX / SP)
#define BATCH (SP * MM)
#define HB 112
#define EB 1024

// ---------------- scratch (device globals; no allocation allowed) ------------
__device__ int d_idx[NMAX];
__device__ int d_hist[HB * SP];
__device__ int d_off[HB * SP];

// [hi | lo] split buffers, K-contiguous rows of width 2*K
__device__ __align__(16) __nv_bfloat16 d_a0[(size_t)NMAX * 2 * DD];
__device__ __align__(16) __nv_bfloat16 d_w0[(size_t)BATCH * H0 * 2 * DD];
__device__ __align__(16) __nv_bfloat16 d_w1[(size_t)BATCH * H1 * 2 * H0];
__device__ __align__(16) __nv_bfloat16 d_w2[(size_t)BATCH * H2 * 2 * H1];
__device__ __align__(16) __nv_bfloat16 d_a1[(size_t)BATCH * GMAX * 2 * H0];
__device__ __align__(16) __nv_bfloat16 d_a2[(size_t)BATCH * GMAX * 2 * H1];
__device__ float d_ps[(size_t)BATCH * GMAX * 6];   // per-row partial W3 dots
__device__ float d_part[EB];

__device__ __forceinline__ float celu_f(float x) {
    return x > 0.f ? x : 0.1f * expm1f(x * 10.0f);
}

// ---------------- PTX helpers (all baseline sm_80+ features) ------------------
__device__ __forceinline__ uint32_t smem_u32(const void* p) {
    uint32_t a;
    asm("{ .reg .u64 t; cvta.to.shared.u64 t, %1; cvt.u32.u64 %0, t; }"
        : "=r"(a) : "l"(p));
    return a;
}
__device__ __forceinline__ void cp16(uint32_t s, const void* g) {
    asm volatile("cp.async.cg.shared.global [%0], [%1], 16;" :: "r"(s), "l"(g));
}
__device__ __forceinline__ void cp_commit() {
    asm volatile("cp.async.commit_group;" ::: "memory");
}
template <int N>
__device__ __forceinline__ void cp_wait() {
    asm volatile("cp.async.wait_group %0;" :: "n"(N) : "memory");
}
__device__ __forceinline__ void ldsm_x4(uint32_t& r0, uint32_t& r1,
                                        uint32_t& r2, uint32_t& r3, uint32_t a) {
    asm volatile("ldmatrix.sync.aligned.m8n8.x4.shared.b16 {%0,%1,%2,%3}, [%4];"
                 : "=r"(r0), "=r"(r1), "=r"(r2), "=r"(r3) : "r"(a));
}
__device__ __forceinline__ void ldsm_x2(uint32_t& r0, uint32_t& r1, uint32_t a) {
    asm volatile("ldmatrix.sync.aligned.m8n8.x2.shared.b16 {%0,%1}, [%2];"
                 : "=r"(r0), "=r"(r1) : "r"(a));
}
__device__ __forceinline__ void mma16816(float* c, const uint32_t* a, const uint32_t* b) {
    asm volatile(
        "mma.sync.aligned.m16n8k16.row.col.f32.bf16.bf16.f32 "
        "{%0,%1,%2,%3}, {%4,%5,%6,%7}, {%8,%9}, {%0,%1,%2,%3};"
        : "+f"(c[0]), "+f"(c[1]), "+f"(c[2]), "+f"(c[3])
        : "r"(a[0]), "r"(a[1]), "r"(a[2]), "r"(a[3]), "r"(b[0]), "r"(b[1]));
}

// ---------------- stable species bucketing (deterministic) -------------------
__global__ void k_hist(const int* __restrict__ sp, int n, int chunk) {
    __shared__ int h[SP];
    if (threadIdx.x < SP) h[threadIdx.x] = 0;
    __syncthreads();
    int b = blockIdx.x;
    int beg = b * chunk, end = min(n, beg + chunk);
    for (int i = beg + threadIdx.x; i < end; i += blockDim.x)
        atomicAdd(&h[sp[i]], 1);
    __syncthreads();
    if (threadIdx.x < SP) d_hist[b * SP + threadIdx.x] = h[threadIdx.x];
}
__global__ void k_scan(int G) {
    int s = threadIdx.x;
    if (s >= SP) return;
    int acc = s * G;
    for (int b = 0; b < HB; b++) { d_off[b * SP + s] = acc; acc += d_hist[b * SP + s]; }
}
__global__ void k_place(const int* __restrict__ sp, int n, int chunk) {
    if (threadIdx.x != 0) return;
    int b = blockIdx.x;
    int beg = b * chunk, end = min(n, beg + chunk);
    int loc[SP];
#pragma unroll
    for (int s = 0; s < SP; s++) loc[s] = d_off[b * SP + s];
    for (int i = beg; i < end; i++) d_idx[loc[sp[i]]++] = i;
}

// ---------------- prep: gather+split AEV, transpose+split weights ------------
__global__ void k_prep_aev(const float* __restrict__ aev) {
    int r = blockIdx.x;
    const float* src = aev + (size_t)d_idx[r] * DD;
    size_t dst = (size_t)r * (2 * DD);
    for (int k = threadIdx.x; k < DD; k += blockDim.x) {
        float v = src[k];
        __nv_bfloat16 h = __float2bfloat16(v);
        d_a0[dst + k] = h;
        d_a0[dst + DD + k] = __float2bfloat16(v - __bfloat162float(h));
    }
}

__global__ void k_wsplit(const float* __restrict__ W, int K, int N, int layer) {
    __shared__ float tile[32][33];
    int bm = blockIdx.z;
    int n0 = blockIdx.x * 32, k0 = blockIdx.y * 32;
    const float* Wp = W + (size_t)bm * K * N;
    for (int r = threadIdx.y; r < 32; r += 8) {
        int k = k0 + r, n = n0 + threadIdx.x;
        tile[r][threadIdx.x] = (k < K && n < N) ? Wp[(size_t)k * N + n] : 0.f;
    }
    __syncthreads();
    __nv_bfloat16* O;
    if (layer == 0)      O = d_w0;
    else if (layer == 1) O = d_w1;
    else                 O = d_w2;
    for (int r = threadIdx.y; r < 32; r += 8) {
        int n = n0 + r, k = k0 + threadIdx.x;
        if (n < N && k < K) {
            float v = tile[threadIdx.x][r];
            __nv_bfloat16 h = __float2bfloat16(v);
            size_t o = ((size_t)bm * N + n) * (size_t)(2 * K) + k;
            O[o] = h;
            O[o + K] = __float2bfloat16(v - __bfloat162float(h));
        }
    }
}

// ---------------- bf16 HMMA batched GEMM (fused 3-product per chunk) ---------
// BM=128, BN=64, BK=16. Per chunk load Ah|Al and Bh|Bl once (packed rows,
// 80B pitch), then D += Ah*Bh + Al*Bh + Ah*Bl.  [drops Al*Bl ~ 2^-18]
// Epilogue: +bias, CELU; LAYER<2 -> hi/lo split store;
//           LAYER==2 -> fused W3 dot -> d_ps partials (no d_h2 round trip).
template <int K, int NOUT, int LAYER>
__global__ void __launch_bounds__(256, 2)
k_mma(const float* __restrict__ bias, const float* __restrict__ w3g, int G) {
    constexpr int BM = 128, BN = 64;
    constexpr int TOTAL = K / 16;
    constexpr int NS = 3;

    // packed rows: [hi 16 elems | lo 16 elems | 8 pad] = 80B pitch (odd*16B)
    __shared__ __align__(16) __nv_bfloat16 As[NS][BM][40];
    __shared__ __align__(16) __nv_bfloat16 Bs[NS][BN][40];

    const int t = threadIdx.x;
    const int lane = t & 31;
    const int wid = t >> 5;
    const int wr = wid >> 1;   // 0..3 -> 32-row slab
    const int wn = wid & 1;    // 0..1 -> 32-col slab
    const int bm = blockIdx.z;
    const int gt = blockIdx.x * BM;
    const int ntb = blockIdx.y * BN;

    const __nv_bfloat16* Ag;
    const __nv_bfloat16* Wg;
    size_t aBase;
    if (LAYER == 0)      { Ag = d_a0; Wg = d_w0; aBase = (size_t)(bm / MM) * G; }
    else if (LAYER == 1) { Ag = d_a1; Wg = d_w1; aBase = (size_t)bm * G; }
    else                 { Ag = d_a2; Wg = d_w2; aBase = (size_t)bm * G; }

    // A: thread t -> row t>>1, 16B segment t&1 (hi and lo)
    const int arow = t >> 1, aseg = t & 1;
    const int growc = min(gt + arow, G - 1);
    const __nv_bfloat16* aSrc =
        Ag + ((size_t)(aBase + growc)) * (size_t)(2 * K) + aseg * 8;
    // B: thread t -> row t>>2, quad t&3: part=quad>>1 (hi/lo), half=quad&1
    const int brow = t >> 2, bpart = (t >> 1) & 1, bhalf = t & 1;
    const int bn = min(ntb + brow, NOUT - 1);
    const __nv_bfloat16* bSrc =
        Wg + ((size_t)bm * NOUT + bn) * (size_t)(2 * K) + bpart * K + bhalf * 8;

    auto load_stage = [&](int st, int it) {
        const int k0 = it * 16;
        cp16(smem_u32(&As[st][arow][aseg * 8]), aSrc + k0);           // hi
        cp16(smem_u32(&As[st][arow][16 + aseg * 8]), aSrc + K + k0);  // lo
        cp16(smem_u32(&Bs[st][brow][bpart * 16 + bhalf * 8]), bSrc + k0);
        cp_commit();
    };

    float acc[2][4][4];
#pragma unroll
    for (int i = 0; i < 2; i++)
#pragma unroll
        for (int j = 0; j < 4; j++)
#pragma unroll
            for (int k = 0; k < 4; k++) acc[i][j][k] = 0.f;

    // ldmatrix lane address offsets (bytes), 80B pitch; lo fragments at +32
    const uint32_t aoff = (uint32_t)((wr * 32 + (lane & 15)) * 80 + (lane >> 4) * 16);
    const uint32_t boff = (uint32_t)((wn * 32 + (lane & 7)) * 80 + ((lane >> 3) & 1) * 16);

#pragma unroll 1
    for (int s = 0; s < NS - 1; s++) load_stage(s, s);

#pragma unroll 1
    for (int i = 0; i < TOTAL; i++) {
        cp_wait<NS - 2>();
        __syncthreads();
        if (i + NS - 1 < TOTAL) load_stage((i + NS - 1) % NS, i + NS - 1);
        else cp_commit();

        const int st = i % NS;
        const uint32_t ab = smem_u32(&As[st][0][0]);
        const uint32_t bb = smem_u32(&Bs[st][0][0]);
        uint32_t ah[2][4], al[2][4], bh[4][2], bl[4][2];
#pragma unroll
        for (int mt = 0; mt < 2; mt++) {
            ldsm_x4(ah[mt][0], ah[mt][1], ah[mt][2], ah[mt][3],
                    ab + aoff + mt * 16 * 80);
            ldsm_x4(al[mt][0], al[mt][1], al[mt][2], al[mt][3],
                    ab + aoff + mt * 16 * 80 + 32);
        }
#pragma unroll
        for (int nt = 0; nt < 4; nt++) {
            ldsm_x2(bh[nt][0], bh[nt][1], bb + boff + nt * 8 * 80);
            ldsm_x2(bl[nt][0], bl[nt][1], bb + boff + nt * 8 * 80 + 32);
        }
#pragma unroll
        for (int mt = 0; mt < 2; mt++)
#pragma unroll
            for (int nt = 0; nt < 4; nt++) {
                mma16816(acc[mt][nt], ah[mt], bh[nt]);
                mma16816(acc[mt][nt], al[mt], bh[nt]);
                mma16816(acc[mt][nt], ah[mt], bl[nt]);
            }
    }

    // -------- epilogue --------
    const float* bp = bias + (size_t)bm * NOUT;
    if (LAYER < 2) {
#pragma unroll
        for (int mt = 0; mt < 2; mt++) {
#pragma unroll
            for (int half = 0; half < 2; half++) {
                const int grow = gt + wr * 32 + mt * 16 + (lane >> 2) + half * 8;
                if (grow >= G) continue;
                size_t rb = ((size_t)bm * G + grow) * (size_t)(2 * NOUT);
#pragma unroll
                for (int nt = 0; nt < 4; nt++) {
                    const int col = ntb + wn * 32 + nt * 8 + (lane & 3) * 2;
                    if (col >= NOUT) continue;
                    float v0 = acc[mt][nt][half * 2 + 0] + __ldg(bp + col);
                    float v1 = acc[mt][nt][half * 2 + 1] + __ldg(bp + col + 1);
                    v0 = celu_f(v0);
                    v1 = celu_f(v1);
                    __nv_bfloat16 h0 = __float2bfloat16(v0);
                    __nv_bfloat16 h1 = __float2bfloat16(v1);
                    __nv_bfloat162 hh, ll;
                    hh.x = h0; hh.y = h1;
                    ll.x = __float2bfloat16(v0 - __bfloat162float(h0));
                    ll.y = __float2bfloat16(v1 - __bfloat162float(h1));
                    __nv_bfloat16* dst = (LAYER == 0) ? d_a1 : d_a2;
                    *(__nv_bfloat162*)(dst + rb + col) = hh;
                    *(__nv_bfloat162*)(dst + rb + NOUT + col) = ll;
                }
            }
        }
    } else {
        // fused last-layer dot: p = sum_cols celu(acc+bias)*w3[col]
        const float* w3 = w3g + (size_t)bm * H2;
#pragma unroll
        for (int mt = 0; mt < 2; mt++) {
#pragma unroll
            for (int half = 0; half < 2; half++) {
                const int grow = gt + wr * 32 + mt * 16 + (lane >> 2) + half * 8;
                float p = 0.f;
#pragma unroll
                for (int nt = 0; nt < 4; nt++) {
                    const int col = ntb + wn * 32 + nt * 8 + (lane & 3) * 2;
                    if (col >= NOUT) continue;
                    float v0 = acc[mt][nt][half * 2 + 0] + __ldg(bp + col);
                    float v1 = acc[mt][nt][half * 2 + 1] + __ldg(bp + col + 1);
                    p = fmaf(celu_f(v0), __ldg(w3 + col), p);
                    p = fmaf(celu_f(v1), __ldg(w3 + col + 1), p);
                }
                // reduce across the 4 lanes holding this row's columns
                p += __shfl_xor_sync(0xFFFFFFFFu, p, 1);
                p += __shfl_xor_sync(0xFFFFFFFFu, p, 2);
                if ((lane & 3) == 0 && grow < G)
                    d_ps[((size_t)bm * G + grow) * 6 + blockIdx.y * 2 + wn] = p;
            }
        }
    }
}

// ---------------- deterministic energy reduction -----------------------------
__global__ void k_energy2(const float* __restrict__ b3, int G) {
    const int R = BATCH * G;
    float sum = 0.f;
    for (int r = blockIdx.x * blockDim.x + threadIdx.x; r < R;
         r += gridDim.x * blockDim.x) {
        const int bm = r / G;
        const float* ps = d_ps + (size_t)r * 6;
        sum += ps[0] + ps[1] + ps[2] + ps[3] + ps[4] + ps[5] + b3[bm];
    }
    __shared__ float sh[256];
    sh[threadIdx.x] = sum;
    __syncthreads();
    for (int s = 128; s > 0; s >>= 1) {
        if (threadIdx.x < s) sh[threadIdx.x] += sh[threadIdx.x + s];
        __syncthreads();
    }
    if (threadIdx.x == 0) d_part[blockIdx.x] = sh[0];
}

__global__ void k_final(float* __restrict__ out) {
    __shared__ float sh[EB];
    const int tid = threadIdx.x;
    sh[tid] = d_part[tid];
    __syncthreads();
    for (int s = EB / 2; s > 0; s >>= 1) {
        if (tid < s) sh[tid] += sh[tid + s];
        __syncthreads();
    }
    if (tid == 0) out[0] = sh[0] * (1.0f / (float)MM);
}

// ---------------- harness entry ----------------------------------------------
extern "C" void kernel_launch(void* const* d_in, const int* in_sizes, int n_in,
                              void* d_out, int out_size) {
    const int* species = (const int*)d_in[0];
    const float* aev = (const float*)d_in[1];
    const float* W0 = (const float*)d_in[2];
    const float* b0 = (const float*)d_in[3];
    const float* W1 = (const float*)d_in[4];
    const float* b1 = (const float*)d_in[5];
    const float* W2 = (const float*)d_in[6];
    const float* b2 = (const float*)d_in[7];
    const float* W3 = (const float*)d_in[8];
    const float* b3 = (const float*)d_in[9];
    float* out = (float*)d_out;

    const int N = in_sizes[0];
    const int G = N / SP;
    const int chunk = (N + HB - 1) / HB;

    // bucketing
    k_hist<<<HB, 256>>>(species, N, chunk);
    k_scan<<<1, 32>>>(G);
    k_place<<<HB, 32>>>(species, N, chunk);

    // prep: gather+split AEV, transpose+split weights
    k_prep_aev<<<N, 256>>>(aev);
    {
        dim3 g0((H0 + 31) / 32, (DD + 31) / 32, BATCH);
        k_wsplit<<<g0, dim3(32, 8)>>>(W0, DD, H0, 0);
        dim3 g1((H1 + 31) / 32, (H0 + 31) / 32, BATCH);
        k_wsplit<<<g1, dim3(32, 8)>>>(W1, H0, H1, 1);
        dim3 g2((H2 + 31) / 32, (H1 + 31) / 32, BATCH);
        k_wsplit<<<g2, dim3(32, 8)>>>(W2, H1, H2, 2);
    }

    const int gtiles = (G + 127) / 128;
    k_mma<DD, H0, 0><<<dim3(gtiles, (H0 + 63) / 64, BATCH), 256>>>(b0, nullptr, G);
    k_mma<H0, H1, 1><<<dim3(gtiles, (H1 + 63) / 64, BATCH), 256>>>(b1, nullptr, G);
    k_mma<H1, H2, 2><<<dim3(gtiles, (H2 + 63) / 64, BATCH), 256>>>(b2, W3, G);

    k_energy2<<<EB, 256>>>(b3, G);
    k_final<<<1, EB>>>(out);
}

// round 9
// speedup vs baseline: 1.3393x; 1.0252x over previous
#include <cuda_runtime.h>
#include <cuda_bf16.h>
#include <cstdint>

#define SP 7
#define MM 8
#define DD 1008
#define H0 256
#define H1 192
#define H2 160
#define NMAX 50400
#define GMAX (NMAX / SP)
#define BATCH (SP * MM)
#define HB 112
#define EB 1024

// ---------------- scratch (device globals; no allocation allowed) ------------
__device__ int d_idx[NMAX];
__device__ int d_hist[HB * SP];
__device__ int d_off[HB * SP];

// [hi | lo] split buffers, K-contiguous rows of width 2*K
__device__ __align__(16) __nv_bfloat16 d_a0[(size_t)NMAX * 2 * DD];
__device__ __align__(16) __nv_bfloat16 d_w0[(size_t)BATCH * H0 * 2 * DD];
__device__ __align__(16) __nv_bfloat16 d_w1[(size_t)BATCH * H1 * 2 * H0];
__device__ __align__(16) __nv_bfloat16 d_w2[(size_t)BATCH * H2 * 2 * H1];
__device__ __align__(16) __nv_bfloat16 d_a1[(size_t)BATCH * GMAX * 2 * H0];
__device__ __align__(16) __nv_bfloat16 d_a2[(size_t)BATCH * GMAX * 2 * H1];
__device__ float d_ps[(size_t)BATCH * GMAX * 6];   // per-row partial W3 dots
__device__ float d_part[EB];

__device__ __forceinline__ float celu_f(float x) {
    return x > 0.f ? x : 0.1f * expm1f(x * 10.0f);
}

// ---------------- PTX helpers (all baseline sm_80+ features) ------------------
__device__ __forceinline__ uint32_t smem_u32(const void* p) {
    uint32_t a;
    asm("{ .reg .u64 t; cvta.to.shared.u64 t, %1; cvt.u32.u64 %0, t; }"
        : "=r"(a) : "l"(p));
    return a;
}
__device__ __forceinline__ void cp16(uint32_t s, const void* g) {
    asm volatile("cp.async.cg.shared.global [%0], [%1], 16;" :: "r"(s), "l"(g));
}
__device__ __forceinline__ void cp_commit() {
    asm volatile("cp.async.commit_group;" ::: "memory");
}
template <int N>
__device__ __forceinline__ void cp_wait() {
    asm volatile("cp.async.wait_group %0;" :: "n"(N) : "memory");
}
__device__ __forceinline__ void ldsm_x4(uint32_t& r0, uint32_t& r1,
                                        uint32_t& r2, uint32_t& r3, uint32_t a) {
    asm volatile("ldmatrix.sync.aligned.m8n8.x4.shared.b16 {%0,%1,%2,%3}, [%4];"
                 : "=r"(r0), "=r"(r1), "=r"(r2), "=r"(r3) : "r"(a));
}
__device__ __forceinline__ void mma16816(float* c, const uint32_t* a, const uint32_t* b) {
    asm volatile(
        "mma.sync.aligned.m16n8k16.row.col.f32.bf16.bf16.f32 "
        "{%0,%1,%2,%3}, {%4,%5,%6,%7}, {%8,%9}, {%0,%1,%2,%3};"
        : "+f"(c[0]), "+f"(c[1]), "+f"(c[2]), "+f"(c[3])
        : "r"(a[0]), "r"(a[1]), "r"(a[2]), "r"(a[3]), "r"(b[0]), "r"(b[1]));
}

// ---------------- stable species bucketing (deterministic) -------------------
__global__ void k_hist(const int* __restrict__ sp, int n, int chunk) {
    __shared__ int h[SP];
    if (threadIdx.x < SP) h[threadIdx.x] = 0;
    __syncthreads();
    int b = blockIdx.x;
    int beg = b * chunk, end = min(n, beg + chunk);
    for (int i = beg + threadIdx.x; i < end; i += blockDim.x)
        atomicAdd(&h[sp[i]], 1);
    __syncthreads();
    if (threadIdx.x < SP) d_hist[b * SP + threadIdx.x] = h[threadIdx.x];
}
__global__ void k_scan(int G) {
    int s = threadIdx.x;
    if (s >= SP) return;
    int acc = s * G;
    for (int b = 0; b < HB; b++) { d_off[b * SP + s] = acc; acc += d_hist[b * SP + s]; }
}
__global__ void k_place(const int* __restrict__ sp, int n, int chunk) {
    if (threadIdx.x != 0) return;
    int b = blockIdx.x;
    int beg = b * chunk, end = min(n, beg + chunk);
    int loc[SP];
#pragma unroll
    for (int s = 0; s < SP; s++) loc[s] = d_off[b * SP + s];
    for (int i = beg; i < end; i++) d_idx[loc[sp[i]]++] = i;
}

// ---------------- prep: gather+split AEV, transpose+split weights ------------
__global__ void k_prep_aev(const float* __restrict__ aev) {
    int r = blockIdx.x;
    const float* src = aev + (size_t)d_idx[r] * DD;
    size_t dst = (size_t)r * (2 * DD);
    for (int k = threadIdx.x; k < DD; k += blockDim.x) {
        float v = src[k];
        __nv_bfloat16 h = __float2bfloat16(v);
        d_a0[dst + k] = h;
        d_a0[dst + DD + k] = __float2bfloat16(v - __bfloat162float(h));
    }
}

__global__ void k_wsplit(const float* __restrict__ W, int K, int N, int layer) {
    __shared__ float tile[32][33];
    int bm = blockIdx.z;
    int n0 = blockIdx.x * 32, k0 = blockIdx.y * 32;
    const float* Wp = W + (size_t)bm * K * N;
    for (int r = threadIdx.y; r < 32; r += 8) {
        int k = k0 + r, n = n0 + threadIdx.x;
        tile[r][threadIdx.x] = (k < K && n < N) ? Wp[(size_t)k * N + n] : 0.f;
    }
    __syncthreads();
    __nv_bfloat16* O;
    if (layer == 0)      O = d_w0;
    else if (layer == 1) O = d_w1;
    else                 O = d_w2;
    for (int r = threadIdx.y; r < 32; r += 8) {
        int n = n0 + r, k = k0 + threadIdx.x;
        if (n < N && k < K) {
            float v = tile[threadIdx.x][r];
            __nv_bfloat16 h = __float2bfloat16(v);
            size_t o = ((size_t)bm * N + n) * (size_t)(2 * K) + k;
            O[o] = h;
            O[o + K] = __float2bfloat16(v - __bfloat162float(h));
        }
    }
}

// ---------------- bf16 HMMA batched GEMM (fused 3-product per chunk) ---------
// BM=128, BN=64, BK=16. Grid = (bm, gtile, ytile): bm fastest so the 8 models
// sharing an A tile (L0) are adjacent in the wave -> A served from L2.
// Per chunk load Ah|Al and Bh|Bl once (80B-pitch packed rows), then
// D += Ah*Bh + Al*Bh + Ah*Bl.  [drops Al*Bl ~ 2^-18]
// Epilogue: +bias, CELU; LAYER<2 -> hi/lo split store;
//           LAYER==2 -> fused W3 dot -> d_ps partials.
template <int K, int NOUT, int LAYER>
__global__ void __launch_bounds__(256, 2)
k_mma(const float* __restrict__ bias, const float* __restrict__ w3g, int G) {
    constexpr int BM = 128, BN = 64;
    constexpr int TOTAL = K / 16;
    constexpr int NS = 3;

    // packed rows: [hi 16 elems | lo 16 elems | 8 pad] = 80B pitch (odd*16B)
    __shared__ __align__(16) __nv_bfloat16 As[NS][BM][40];
    __shared__ __align__(16) __nv_bfloat16 Bs[NS][BN][40];

    const int t = threadIdx.x;
    const int lane = t & 31;
    const int wid = t >> 5;
    const int wr = wid >> 1;   // 0..3 -> 32-row slab
    const int wn = wid & 1;    // 0..1 -> 32-col slab
    const int bm = blockIdx.x;          // fastest: models adjacent
    const int gt = blockIdx.y * BM;
    const int ytile = blockIdx.z;
    const int ntb = ytile * BN;

    const __nv_bfloat16* Ag;
    const __nv_bfloat16* Wg;
    size_t aBase;
    if (LAYER == 0)      { Ag = d_a0; Wg = d_w0; aBase = (size_t)(bm / MM) * G; }
    else if (LAYER == 1) { Ag = d_a1; Wg = d_w1; aBase = (size_t)bm * G; }
    else                 { Ag = d_a2; Wg = d_w2; aBase = (size_t)bm * G; }

    // A: thread t -> row t>>1, 16B segment t&1 (hi and lo)
    const int arow = t >> 1, aseg = t & 1;
    const int growc = min(gt + arow, G - 1);
    const __nv_bfloat16* aSrc =
        Ag + ((size_t)(aBase + growc)) * (size_t)(2 * K) + aseg * 8;
    // B: thread t -> row t>>2, quad t&3: part=quad>>1 (hi/lo), half=quad&1
    const int brow = t >> 2, bpart = (t >> 1) & 1, bhalf = t & 1;
    const int bn = min(ntb + brow, NOUT - 1);
    const __nv_bfloat16* bSrc =
        Wg + ((size_t)bm * NOUT + bn) * (size_t)(2 * K) + bpart * K + bhalf * 8;

    auto load_stage = [&](int st, int it) {
        const int k0 = it * 16;
        cp16(smem_u32(&As[st][arow][aseg * 8]), aSrc + k0);           // hi
        cp16(smem_u32(&As[st][arow][16 + aseg * 8]), aSrc + K + k0);  // lo
        cp16(smem_u32(&Bs[st][brow][bpart * 16 + bhalf * 8]), bSrc + k0);
        cp_commit();
    };

    float acc[2][4][4];
#pragma unroll
    for (int i = 0; i < 2; i++)
#pragma unroll
        for (int j = 0; j < 4; j++)
#pragma unroll
            for (int k = 0; k < 4; k++) acc[i][j][k] = 0.f;

    // ldmatrix lane address offsets (bytes), 80B pitch; lo fragments at +32
    const uint32_t aoff = (uint32_t)((wr * 32 + (lane & 15)) * 80 + (lane >> 4) * 16);
    // B x4 mapping: lanes 0-7 -> rows r, 8-15 -> rows r (+16B),
    //               16-23 -> rows r+8, 24-31 -> rows r+8 (+16B)
    const uint32_t boff4 = (uint32_t)(
        (wn * 32 + (lane & 7) + ((lane >> 4) << 3)) * 80 + (((lane >> 3) & 1) * 16));

#pragma unroll 1
    for (int s = 0; s < NS - 1; s++) load_stage(s, s);

#pragma unroll 1
    for (int i = 0; i < TOTAL; i++) {
        cp_wait<NS - 2>();
        __syncthreads();
        if (i + NS - 1 < TOTAL) load_stage((i + NS - 1) % NS, i + NS - 1);
        else cp_commit();

        const int st = i % NS;
        const uint32_t ab = smem_u32(&As[st][0][0]);
        const uint32_t bb = smem_u32(&Bs[st][0][0]);
        uint32_t ah[2][4], al[2][4], bh[4][2], bl[4][2];
#pragma unroll
        for (int mt = 0; mt < 2; mt++) {
            ldsm_x4(ah[mt][0], ah[mt][1], ah[mt][2], ah[mt][3],
                    ab + aoff + mt * 16 * 80);
            ldsm_x4(al[mt][0], al[mt][1], al[mt][2], al[mt][3],
                    ab + aoff + mt * 16 * 80 + 32);
        }
        // paired B loads: one x4 covers nt and nt+1
        ldsm_x4(bh[0][0], bh[0][1], bh[1][0], bh[1][1], bb + boff4);
        ldsm_x4(bh[2][0], bh[2][1], bh[3][0], bh[3][1], bb + boff4 + 16 * 80);
        ldsm_x4(bl[0][0], bl[0][1], bl[1][0], bl[1][1], bb + boff4 + 32);
        ldsm_x4(bl[2][0], bl[2][1], bl[3][0], bl[3][1], bb + boff4 + 16 * 80 + 32);
#pragma unroll
        for (int mt = 0; mt < 2; mt++)
#pragma unroll
            for (int nt = 0; nt < 4; nt++) {
                mma16816(acc[mt][nt], ah[mt], bh[nt]);
                mma16816(acc[mt][nt], al[mt], bh[nt]);
                mma16816(acc[mt][nt], ah[mt], bl[nt]);
            }
    }

    // -------- epilogue --------
    const float* bp = bias + (size_t)bm * NOUT;
    if (LAYER < 2) {
#pragma unroll
        for (int mt = 0; mt < 2; mt++) {
#pragma unroll
            for (int half = 0; half < 2; half++) {
                const int grow = gt + wr * 32 + mt * 16 + (lane >> 2) + half * 8;
                if (grow >= G) continue;
                size_t rb = ((size_t)bm * G + grow) * (size_t)(2 * NOUT);
#pragma unroll
                for (int nt = 0; nt < 4; nt++) {
                    const int col = ntb + wn * 32 + nt * 8 + (lane & 3) * 2;
                    if (col >= NOUT) continue;
                    float v0 = acc[mt][nt][half * 2 + 0] + __ldg(bp + col);
                    float v1 = acc[mt][nt][half * 2 + 1] + __ldg(bp + col + 1);
                    v0 = celu_f(v0);
                    v1 = celu_f(v1);
                    __nv_bfloat16 h0 = __float2bfloat16(v0);
                    __nv_bfloat16 h1 = __float2bfloat16(v1);
                    __nv_bfloat162 hh, ll;
                    hh.x = h0; hh.y = h1;
                    ll.x = __float2bfloat16(v0 - __bfloat162float(h0));
                    ll.y = __float2bfloat16(v1 - __bfloat162float(h1));
                    __nv_bfloat16* dst = (LAYER == 0) ? d_a1 : d_a2;
                    *(__nv_bfloat162*)(dst + rb + col) = hh;
                    *(__nv_bfloat162*)(dst + rb + NOUT + col) = ll;
                }
            }
        }
    } else {
        // fused last-layer dot: p = sum_cols celu(acc+bias)*w3[col]
        const float* w3 = w3g + (size_t)bm * H2;
#pragma unroll
        for (int mt = 0; mt < 2; mt++) {
#pragma unroll
            for (int half = 0; half < 2; half++) {
                const int grow = gt + wr * 32 + mt * 16 + (lane >> 2) + half * 8;
                float p = 0.f;
#pragma unroll
                for (int nt = 0; nt < 4; nt++) {
                    const int col = ntb + wn * 32 + nt * 8 + (lane & 3) * 2;
                    if (col >= NOUT) continue;
                    float v0 = acc[mt][nt][half * 2 + 0] + __ldg(bp + col);
                    float v1 = acc[mt][nt][half * 2 + 1] + __ldg(bp + col + 1);
                    p = fmaf(celu_f(v0), __ldg(w3 + col), p);
                    p = fmaf(celu_f(v1), __ldg(w3 + col + 1), p);
                }
                // reduce across the 4 lanes holding this row's columns
                p += __shfl_xor_sync(0xFFFFFFFFu, p, 1);
                p += __shfl_xor_sync(0xFFFFFFFFu, p, 2);
                if ((lane & 3) == 0 && grow < G)
                    d_ps[((size_t)bm * G + grow) * 6 + ytile * 2 + wn] = p;
            }
        }
    }
}

// ---------------- deterministic energy reduction -----------------------------
__global__ void k_energy2(const float* __restrict__ b3, int G) {
    const int R = BATCH * G;
    float sum = 0.f;
    for (int r = blockIdx.x * blockDim.x + threadIdx.x; r < R;
         r += gridDim.x * blockDim.x) {
        const int bm = r / G;
        const float* ps = d_ps + (size_t)r * 6;
        sum += ps[0] + ps[1] + ps[2] + ps[3] + ps[4] + ps[5] + b3[bm];
    }
    __shared__ float sh[256];
    sh[threadIdx.x] = sum;
    __syncthreads();
    for (int s = 128; s > 0; s >>= 1) {
        if (threadIdx.x < s) sh[threadIdx.x] += sh[threadIdx.x + s];
        __syncthreads();
    }
    if (threadIdx.x == 0) d_part[blockIdx.x] = sh[0];
}

__global__ void k_final(float* __restrict__ out) {
    __shared__ float sh[EB];
    const int tid = threadIdx.x;
    sh[tid] = d_part[tid];
    __syncthreads();
    for (int s = EB / 2; s > 0; s >>= 1) {
        if (tid < s) sh[tid] += sh[tid + s];
        __syncthreads();
    }
    if (tid == 0) out[0] = sh[0] * (1.0f / (float)MM);
}

// ---------------- harness entry ----------------------------------------------
extern "C" void kernel_launch(void* const* d_in, const int* in_sizes, int n_in,
                              void* d_out, int out_size) {
    const int* species = (const int*)d_in[0];
    const float* aev = (const float*)d_in[1];
    const float* W0 = (const float*)d_in[2];
    const float* b0 = (const float*)d_in[3];
    const float* W1 = (const float*)d_in[4];
    const float* b1 = (const float*)d_in[5];
    const float* W2 = (const float*)d_in[6];
    const float* b2 = (const float*)d_in[7];
    const float* W3 = (const float*)d_in[8];
    const float* b3 = (const float*)d_in[9];
    float* out = (float*)d_out;

    const int N = in_sizes[0];
    const int G = N / SP;
    const int chunk = (N + HB - 1) / HB;

    // bucketing
    k_hist<<<HB, 256>>>(species, N, chunk);
    k_scan<<<1, 32>>>(G);
    k_place<<<HB, 32>>>(species, N, chunk);

    // prep: gather+split AEV, transpose+split weights
    k_prep_aev<<<N, 256>>>(aev);
    {
        dim3 g0((H0 + 31) / 32, (DD + 31) / 32, BATCH);
        k_wsplit<<<g0, dim3(32, 8)>>>(W0, DD, H0, 0);
        dim3 g1((H1 + 31) / 32, (H0 + 31) / 32, BATCH);
        k_wsplit<<<g1, dim3(32, 8)>>>(W1, H0, H1, 1);
        dim3 g2((H2 + 31) / 32, (H1 + 31) / 32, BATCH);
        k_wsplit<<<g2, dim3(32, 8)>>>(W2, H1, H2, 2);
    }

    const int gtiles = (G + 127) / 128;
    k_mma<DD, H0, 0><<<dim3(BATCH, gtiles, (H0 + 63) / 64), 256>>>(b0, nullptr, G);
    k_mma<H0, H1, 1><<<dim3(BATCH, gtiles, (H1 + 63) / 64), 256>>>(b1, nullptr, G);
    k_mma<H1, H2, 2><<<dim3(BATCH, gtiles, (H2 + 63) / 64), 256>>>(b2, W3, G);

    k_energy2<<<EB, 256>>>(b3, G);
    k_final<<<1, EB>>>(out);
}

// round 10
// speedup vs baseline: 1.9250x; 1.4373x over previous
#include <cuda_runtime.h>
#include <cuda_fp16.h>
#include <cstdint>

#define SP 7
#define MM 8
#define DD 1008
#define H0 256
#define H1 192
#define H2 160
#define NMAX 50400
#define GMAX (NMAX / SP)
#define BATCH (SP * MM)
#define HB 112
#define EB 1024

// ---------------- scratch (device globals; no allocation allowed) ------------
__device__ int d_idx[NMAX];
__device__ int d_hist[HB * SP];
__device__ int d_off[HB * SP];

// Activations: fp16 [hi | lo] split, rows of width 2*K. Weights: single fp16.
__device__ __align__(16) __half d_a0[(size_t)NMAX * 2 * DD];
__device__ __align__(16) __half d_w0[(size_t)BATCH * H0 * DD];
__device__ __align__(16) __half d_w1[(size_t)BATCH * H1 * H0];
__device__ __align__(16) __half d_w2[(size_t)BATCH * H2 * H1];
__device__ __align__(16) __half d_a1[(size_t)BATCH * GMAX * 2 * H0];
__device__ __align__(16) __half d_a2[(size_t)BATCH * GMAX * 2 * H1];
__device__ float d_ps[(size_t)BATCH * GMAX * 6];   // per-row partial W3 dots
__device__ float d_part[EB];

__device__ __forceinline__ float celu_f(float x) {
    return x > 0.f ? x : 0.1f * expm1f(x * 10.0f);
}

// ---------------- PTX helpers (all baseline sm_80+ features) ------------------
__device__ __forceinline__ uint32_t smem_u32(const void* p) {
    uint32_t a;
    asm("{ .reg .u64 t; cvta.to.shared.u64 t, %1; cvt.u32.u64 %0, t; }"
        : "=r"(a) : "l"(p));
    return a;
}
__device__ __forceinline__ void cp16(uint32_t s, const void* g) {
    asm volatile("cp.async.cg.shared.global [%0], [%1], 16;" :: "r"(s), "l"(g));
}
__device__ __forceinline__ void cp_commit() {
    asm volatile("cp.async.commit_group;" ::: "memory");
}
template <int N>
__device__ __forceinline__ void cp_wait() {
    asm volatile("cp.async.wait_group %0;" :: "n"(N) : "memory");
}
__device__ __forceinline__ void ldsm_x4(uint32_t& r0, uint32_t& r1,
                                        uint32_t& r2, uint32_t& r3, uint32_t a) {
    asm volatile("ldmatrix.sync.aligned.m8n8.x4.shared.b16 {%0,%1,%2,%3}, [%4];"
                 : "=r"(r0), "=r"(r1), "=r"(r2), "=r"(r3) : "r"(a));
}
__device__ __forceinline__ void mma16816(float* c, const uint32_t* a, const uint32_t* b) {
    asm volatile(
        "mma.sync.aligned.m16n8k16.row.col.f32.f16.f16.f32 "
        "{%0,%1,%2,%3}, {%4,%5,%6,%7}, {%8,%9}, {%0,%1,%2,%3};"
        : "+f"(c[0]), "+f"(c[1]), "+f"(c[2]), "+f"(c[3])
        : "r"(a[0]), "r"(a[1]), "r"(a[2]), "r"(a[3]), "r"(b[0]), "r"(b[1]));
}

// ---------------- stable species bucketing (deterministic) -------------------
__global__ void k_hist(const int* __restrict__ sp, int n, int chunk) {
    __shared__ int h[SP];
    if (threadIdx.x < SP) h[threadIdx.x] = 0;
    __syncthreads();
    int b = blockIdx.x;
    int beg = b * chunk, end = min(n, beg + chunk);
    for (int i = beg + threadIdx.x; i < end; i += blockDim.x)
        atomicAdd(&h[sp[i]], 1);
    __syncthreads();
    if (threadIdx.x < SP) d_hist[b * SP + threadIdx.x] = h[threadIdx.x];
}
__global__ void k_scan(int G) {
    int s = threadIdx.x;
    if (s >= SP) return;
    int acc = s * G;
    for (int b = 0; b < HB; b++) { d_off[b * SP + s] = acc; acc += d_hist[b * SP + s]; }
}
__global__ void k_place(const int* __restrict__ sp, int n, int chunk) {
    if (threadIdx.x != 0) return;
    int b = blockIdx.x;
    int beg = b * chunk, end = min(n, beg + chunk);
    int loc[SP];
#pragma unroll
    for (int s = 0; s < SP; s++) loc[s] = d_off[b * SP + s];
    for (int i = beg; i < end; i++) d_idx[loc[sp[i]]++] = i;
}

// ---------------- prep: gather+split AEV, transpose weights ------------------
__global__ void k_prep_aev(const float* __restrict__ aev) {
    int r = blockIdx.x;
    const float* src = aev + (size_t)d_idx[r] * DD;
    size_t dst = (size_t)r * (2 * DD);
    for (int k = threadIdx.x; k < DD; k += blockDim.x) {
        float v = src[k];
        __half h = __float2half(v);
        d_a0[dst + k] = h;
        d_a0[dst + DD + k] = __float2half(v - __half2float(h));
    }
}

__global__ void k_wsplit(const float* __restrict__ W, int K, int N, int layer) {
    __shared__ float tile[32][33];
    int bm = blockIdx.z;
    int n0 = blockIdx.x * 32, k0 = blockIdx.y * 32;
    const float* Wp = W + (size_t)bm * K * N;
    for (int r = threadIdx.y; r < 32; r += 8) {
        int k = k0 + r, n = n0 + threadIdx.x;
        tile[r][threadIdx.x] = (k < K && n < N) ? Wp[(size_t)k * N + n] : 0.f;
    }
    __syncthreads();
    __half* O;
    if (layer == 0)      O = d_w0;
    else if (layer == 1) O = d_w1;
    else                 O = d_w2;
    for (int r = threadIdx.y; r < 32; r += 8) {
        int n = n0 + r, k = k0 + threadIdx.x;
        if (n < N && k < K)
            O[((size_t)bm * N + n) * (size_t)K + k] = __float2half(tile[threadIdx.x][r]);
    }
}

// ---------------- fp16 HMMA batched GEMM (2-product per chunk) ---------------
// BM=128, BN=64, BK=16. Grid = (bm, gtile, ytile): bm fastest (L0 A reuse in L2).
// Per chunk: load Ah|Al (80B-pitch packed rows) and B (48B pitch), then
// D += Ah*B + Al*B.  A exact to ~2^-22; B fp16-rounded (dropped A*epsB ~ 2^-12).
// Epilogue: +bias, CELU; LAYER<2 -> fp16 hi/lo split store;
//           LAYER==2 -> fused W3 dot -> d_ps partials.
template <int K, int NOUT, int LAYER>
__global__ void __launch_bounds__(256, 2)
k_mma(const float* __restrict__ bias, const float* __restrict__ w3g, int G) {
    constexpr int BM = 128, BN = 64;
    constexpr int TOTAL = K / 16;
    constexpr int NS = 3;

    // A rows: [hi 16 | lo 16 | 8 pad] = 80B pitch; B rows: [16 | 8 pad] = 48B
    __shared__ __align__(16) __half As[NS][BM][40];
    __shared__ __align__(16) __half Bs[NS][BN][24];

    const int t = threadIdx.x;
    const int lane = t & 31;
    const int wid = t >> 5;
    const int wr = wid >> 1;   // 0..3 -> 32-row slab
    const int wn = wid & 1;    // 0..1 -> 32-col slab
    const int bm = blockIdx.x;          // fastest: models adjacent
    const int gt = blockIdx.y * BM;
    const int ytile = blockIdx.z;
    const int ntb = ytile * BN;

    const __half* Ag;
    const __half* Wg;
    size_t aBase;
    if (LAYER == 0)      { Ag = d_a0; Wg = d_w0; aBase = (size_t)(bm / MM) * G; }
    else if (LAYER == 1) { Ag = d_a1; Wg = d_w1; aBase = (size_t)bm * G; }
    else                 { Ag = d_a2; Wg = d_w2; aBase = (size_t)bm * G; }

    // A: thread t -> row t>>1, 16B segment t&1 (hi and lo)
    const int arow = t >> 1, aseg = t & 1;
    const int growc = min(gt + arow, G - 1);
    const __half* aSrc =
        Ag + ((size_t)(aBase + growc)) * (size_t)(2 * K) + aseg * 8;
    // B: threads 0..127 -> row t>>1, segment t&1
    const int brow = t >> 1, bseg = t & 1;
    const int bn = min(ntb + brow, NOUT - 1);
    const __half* bSrc =
        Wg + ((size_t)bm * NOUT + bn) * (size_t)K + bseg * 8;

    auto load_stage = [&](int st, int it) {
        const int k0 = it * 16;
        cp16(smem_u32(&As[st][arow][aseg * 8]), aSrc + k0);           // hi
        cp16(smem_u32(&As[st][arow][16 + aseg * 8]), aSrc + K + k0);  // lo
        if (t < 128) cp16(smem_u32(&Bs[st][brow][bseg * 8]), bSrc + k0);
        cp_commit();
    };

    float acc[2][4][4];
#pragma unroll
    for (int i = 0; i < 2; i++)
#pragma unroll
        for (int j = 0; j < 4; j++)
#pragma unroll
            for (int k = 0; k < 4; k++) acc[i][j][k] = 0.f;

    // ldmatrix lane address offsets (bytes)
    const uint32_t aoff = (uint32_t)((wr * 32 + (lane & 15)) * 80 + (lane >> 4) * 16);
    // paired-B x4: lanes 0-7 rows r seg0, 8-15 rows r seg1,
    //              16-23 rows r+8 seg0, 24-31 rows r+8 seg1  (48B pitch)
    const uint32_t boff4 = (uint32_t)(
        (wn * 32 + (lane & 7) + ((lane >> 4) << 3)) * 48 + (((lane >> 3) & 1) * 16));

#pragma unroll 1
    for (int s = 0; s < NS - 1; s++) load_stage(s, s);

#pragma unroll 1
    for (int i = 0; i < TOTAL; i++) {
        cp_wait<NS - 2>();
        __syncthreads();
        if (i + NS - 1 < TOTAL) load_stage((i + NS - 1) % NS, i + NS - 1);
        else cp_commit();

        const int st = i % NS;
        const uint32_t ab = smem_u32(&As[st][0][0]);
        const uint32_t bb = smem_u32(&Bs[st][0][0]);
        uint32_t ah[2][4], al[2][4], bf[4][2];
#pragma unroll
        for (int mt = 0; mt < 2; mt++) {
            ldsm_x4(ah[mt][0], ah[mt][1], ah[mt][2], ah[mt][3],
                    ab + aoff + mt * 16 * 80);
            ldsm_x4(al[mt][0], al[mt][1], al[mt][2], al[mt][3],
                    ab + aoff + mt * 16 * 80 + 32);
        }
        ldsm_x4(bf[0][0], bf[0][1], bf[1][0], bf[1][1], bb + boff4);
        ldsm_x4(bf[2][0], bf[2][1], bf[3][0], bf[3][1], bb + boff4 + 16 * 48);
#pragma unroll
        for (int mt = 0; mt < 2; mt++)
#pragma unroll
            for (int nt = 0; nt < 4; nt++) {
                mma16816(acc[mt][nt], ah[mt], bf[nt]);
                mma16816(acc[mt][nt], al[mt], bf[nt]);
            }
    }

    // -------- epilogue --------
    const float* bp = bias + (size_t)bm * NOUT;
    if (LAYER < 2) {
#pragma unroll
        for (int mt = 0; mt < 2; mt++) {
#pragma unroll
            for (int half = 0; half < 2; half++) {
                const int grow = gt + wr * 32 + mt * 16 + (lane >> 2) + half * 8;
                if (grow >= G) continue;
                size_t rb = ((size_t)bm * G + grow) * (size_t)(2 * NOUT);
#pragma unroll
                for (int nt = 0; nt < 4; nt++) {
                    const int col = ntb + wn * 32 + nt * 8 + (lane & 3) * 2;
                    if (col >= NOUT) continue;
                    float v0 = acc[mt][nt][half * 2 + 0] + __ldg(bp + col);
                    float v1 = acc[mt][nt][half * 2 + 1] + __ldg(bp + col + 1);
                    v0 = celu_f(v0);
                    v1 = celu_f(v1);
                    __half h0 = __float2half(v0);
                    __half h1 = __float2half(v1);
                    __half2 hh, ll;
                    hh.x = h0; hh.y = h1;
                    ll.x = __float2half(v0 - __half2float(h0));
                    ll.y = __float2half(v1 - __half2float(h1));
                    __half* dst = (LAYER == 0) ? d_a1 : d_a2;
                    *(__half2*)(dst + rb + col) = hh;
                    *(__half2*)(dst + rb + NOUT + col) = ll;
                }
            }
        }
    } else {
        // fused last-layer dot: p = sum_cols celu(acc+bias)*w3[col]
        const float* w3 = w3g + (size_t)bm * H2;
#pragma unroll
        for (int mt = 0; mt < 2; mt++) {
#pragma unroll
            for (int half = 0; half < 2; half++) {
                const int grow = gt + wr * 32 + mt * 16 + (lane >> 2) + half * 8;
                float p = 0.f;
#pragma unroll
                for (int nt = 0; nt < 4; nt++) {
                    const int col = ntb + wn * 32 + nt * 8 + (lane & 3) * 2;
                    if (col >= NOUT) continue;
                    float v0 = acc[mt][nt][half * 2 + 0] + __ldg(bp + col);
                    float v1 = acc[mt][nt][half * 2 + 1] + __ldg(bp + col + 1);
                    p = fmaf(celu_f(v0), __ldg(w3 + col), p);
                    p = fmaf(celu_f(v1), __ldg(w3 + col + 1), p);
                }
                // reduce across the 4 lanes holding this row's columns
                p += __shfl_xor_sync(0xFFFFFFFFu, p, 1);
                p += __shfl_xor_sync(0xFFFFFFFFu, p, 2);
                if ((lane & 3) == 0 && grow < G)
                    d_ps[((size_t)bm * G + grow) * 6 + ytile * 2 + wn] = p;
            }
        }
    }
}

// ---------------- deterministic energy reduction -----------------------------
__global__ void k_energy2(const float* __restrict__ b3, int G) {
    const int R = BATCH * G;
    float sum = 0.f;
    for (int r = blockIdx.x * blockDim.x + threadIdx.x; r < R;
         r += gridDim.x * blockDim.x) {
        const int bm = r / G;
        const float* ps = d_ps + (size_t)r * 6;
        sum += ps[0] + ps[1] + ps[2] + ps[3] + ps[4] + ps[5] + b3[bm];
    }
    __shared__ float sh[256];
    sh[threadIdx.x] = sum;
    __syncthreads();
    for (int s = 128; s > 0; s >>= 1) {
        if (threadIdx.x < s) sh[threadIdx.x] += sh[threadIdx.x + s];
        __syncthreads();
    }
    if (threadIdx.x == 0) d_part[blockIdx.x] = sh[0];
}

__global__ void k_final(float* __restrict__ out) {
    __shared__ float sh[EB];
    const int tid = threadIdx.x;
    sh[tid] = d_part[tid];
    __syncthreads();
    for (int s = EB / 2; s > 0; s >>= 1) {
        if (tid < s) sh[tid] += sh[tid + s];
        __syncthreads();
    }
    if (tid == 0) out[0] = sh[0] * (1.0f / (float)MM);
}

// ---------------- harness entry ----------------------------------------------
extern "C" void kernel_launch(void* const* d_in, const int* in_sizes, int n_in,
                              void* d_out, int out_size) {
    const int* species = (const int*)d_in[0];
    const float* aev = (const float*)d_in[1];
    const float* W0 = (const float*)d_in[2];
    const float* b0 = (const float*)d_in[3];
    const float* W1 = (const float*)d_in[4];
    const float* b1 = (const float*)d_in[5];
    const float* W2 = (const float*)d_in[6];
    const float* b2 = (const float*)d_in[7];
    const float* W3 = (const float*)d_in[8];
    const float* b3 = (const float*)d_in[9];
    float* out = (float*)d_out;

    const int N = in_sizes[0];
    const int G = N / SP;
    const int chunk = (N + HB - 1) / HB;

    // bucketing
    k_hist<<<HB, 256>>>(species, N, chunk);
    k_scan<<<1, 32>>>(G);
    k_place<<<HB, 32>>>(species, N, chunk);

    // prep: gather+split AEV, transpose weights (fp16)
    k_prep_aev<<<N, 256>>>(aev);
    {
        dim3 g0((H0 + 31) / 32, (DD + 31) / 32, BATCH);
        k_wsplit<<<g0, dim3(32, 8)>>>(W0, DD, H0, 0);
        dim3 g1((H1 + 31) / 32, (H0 + 31) / 32, BATCH);
        k_wsplit<<<g1, dim3(32, 8)>>>(W1, H0, H1, 1);
        dim3 g2((H2 + 31) / 32, (H1 + 31) / 32, BATCH);
        k_wsplit<<<g2, dim3(32, 8)>>>(W2, H1, H2, 2);
    }

    const int gtiles = (G + 127) / 128;
    k_mma<DD, H0, 0><<<dim3(BATCH, gtiles, (H0 + 63) / 64), 256>>>(b0, nullptr, G);
    k_mma<H0, H1, 1><<<dim3(BATCH, gtiles, (H1 + 63) / 64), 256>>>(b1, nullptr, G);
    k_mma<H1, H2, 2><<<dim3(BATCH, gtiles, (H2 + 63) / 64), 256>>>(b2, W3, G);

    k_energy2<<<EB, 256>>>(b3, G);
    k_final<<<1, EB>>>(out);
}